// round 16
// baseline (speedup 1.0000x reference)
#include <cuda_runtime.h>
#include <cuda_fp16.h>
#include <mma.h>
#include <math.h>
#include <stdint.h>

using namespace nvcuda;

#define BTOK 4096
#define CDIM 1024
#define HDIM 4096
#define NEXP 8
#define ERWKV 6
#define MAXS (2*BTOK)
#define MIDROWS (MAXS+256)

#define OUT_VF   (BTOK*CDIM)
#define OUT_WIN  (2*BTOK*CDIM)
#define OUT_COST (OUT_WIN + 2*BTOK)
#define OUT_DIFF (OUT_COST + BTOK)
#define OUT_AFF  (OUT_DIFF + BTOK)

// ---------------- SMEM layouts ----------------
#define ROWE   72                      // A row elements (144B)
#define ABUFE  (256*ROWE)              // 18432 elements (36864B) per A buffer
#define BBUFB  (64*272)                // 17408 bytes per B buffer
#define STAGE3B (4*ABUFE + 2*BBUFB)    // 3-pass stage (Wa), 2 stages
#define SMEM3_BYTES (2*STAGE3B + 2048) // 219136
#define STAGE1B (2*ABUFE + BBUFB)      // 1-pass stage, 3 stages
#define SMEM1_BYTES (3*STAGE1B + 2048) // 164864

// ---------------- scratch (static device memory) ----------------
__device__ __half g_xln_h[BTOK*CDIM], g_xln_l[BTOK*CDIM];
__device__ float g_x2[BTOK*CDIM];
__device__ __half g_hr_h[(size_t)BTOK*2*CDIM];   // [tok][0:1024)=h, [1024:2048)=rs (hi only)
__device__ __half g_z_h[BTOK*CDIM];
__device__ __half g_mid_h[(size_t)MIDROWS*HDIM];
__device__ float g_slot0[BTOK*CDIM], g_slot1[BTOK*CDIM];

// fp16 weights in ORIGINAL [K][N] layout (no transpose)
__device__ __half g_Wa_h[CDIM*CDIM], g_Wa_l[CDIM*CDIM];
__device__ __half g_Ws_h[CDIM*CDIM];
__device__ __half g_Wb_h[(size_t)2*CDIM*CDIM];
__device__ __half g_Wk_h[(size_t)ERWKV*CDIM*HDIM];
__device__ __half g_Wv_h[(size_t)ERWKV*HDIM*CDIM];
__device__ __half g_W1_h[2*CDIM*CDIM];
__device__ __half g_W2_h[2*CDIM*CDIM];

// routing
__device__ int   g_win[2*BTOK];
__device__ float g_wt [2*BTOK];
__device__ int   g_cnt[NEXP];
__device__ int   g_off[NEXP+1];
__device__ int   g_cur[NEXP];
__device__ int   g_tok[MAXS];
__device__ float g_gate[MAXS];
__device__ int   g_rank[MAXS];
__device__ int   g_toff[2][NEXP+1];
__device__ unsigned int g_ctr[2];

// ---------------- helpers ----------------
__device__ __forceinline__ uint32_t smem_to_u32(const void* p) {
    uint32_t a;
    asm("{ .reg .u64 t; cvta.to.shared.u64 t, %1; cvt.u32.u64 %0, t; }" : "=r"(a) : "l"(p));
    return a;
}
#define CP_ASYNC16(dst, src) \
    asm volatile("cp.async.cg.shared.global [%0], [%1], 16;" :: "r"(dst), "l"(src) : "memory")
#define CP_COMMIT() asm volatile("cp.async.commit_group;" ::: "memory")
#define CP_WAIT(n)  asm volatile("cp.async.wait_group %0;" :: "n"(n) : "memory")

__device__ __forceinline__ float gelu_tanh(float x){
    float x3 = x*x*x;
    return 0.5f*x*(1.0f + tanhf(0.7978845608028654f*(x + 0.044715f*x3)));
}
__device__ __forceinline__ void split_store(__half* ph, __half* pl, size_t o, float v){
    __half hi = __float2half(v);
    ph[o] = hi;
    pl[o] = __float2half(v - __half2float(hi));
}

// ---------------- merged weight convert: all 8 weights in ONE launch ----------------
// block-range dispatch (2048 elements per block)
#define CBLK_C2   512                          // CDIM*CDIM / 2048
#define CBLK_KH   12288                        // ERWKV*CDIM*HDIM / 2048
#define CB_WA   0
#define CB_WS   (CB_WA  + CBLK_C2)
#define CB_WBH  (CB_WS  + CBLK_C2)
#define CB_WBS  (CB_WBH + CBLK_C2)
#define CB_WK   (CB_WBS + CBLK_C2)
#define CB_WV   (CB_WK  + CBLK_KH)
#define CB_W1   (CB_WV  + CBLK_KH)
#define CB_W2   (CB_W1  + 2*CBLK_C2)
#define CB_TOT  (CB_W2  + 2*CBLK_C2)           // 28672

__device__ __forceinline__ void conv8(const float* __restrict__ src, __half* __restrict__ dh,
                                      __half* __restrict__ dl, long long i)
{
    float4 v0 = *(const float4*)(src+i);
    float4 v1 = *(const float4*)(src+i+4);
    __half2 a = __floats2half2_rn(v0.x, v0.y);
    __half2 b = __floats2half2_rn(v0.z, v0.w);
    __half2 c = __floats2half2_rn(v1.x, v1.y);
    __half2 d = __floats2half2_rn(v1.z, v1.w);
    uint4 o;
    o.x = *reinterpret_cast<unsigned*>(&a);
    o.y = *reinterpret_cast<unsigned*>(&b);
    o.z = *reinterpret_cast<unsigned*>(&c);
    o.w = *reinterpret_cast<unsigned*>(&d);
    *(uint4*)(dh+i) = o;
    if (dl){
        __half2 la = __floats2half2_rn(v0.x-__low2float(a), v0.y-__high2float(a));
        __half2 lb = __floats2half2_rn(v0.z-__low2float(b), v0.w-__high2float(b));
        __half2 lc = __floats2half2_rn(v1.x-__low2float(c), v1.y-__high2float(c));
        __half2 ld = __floats2half2_rn(v1.z-__low2float(d), v1.w-__high2float(d));
        uint4 ol;
        ol.x = *reinterpret_cast<unsigned*>(&la);
        ol.y = *reinterpret_cast<unsigned*>(&lb);
        ol.z = *reinterpret_cast<unsigned*>(&lc);
        ol.w = *reinterpret_cast<unsigned*>(&ld);
        *(uint4*)(dl+i) = ol;
    }
}

__global__ void k_convert_all(
    const float* __restrict__ Wa,  const float* __restrict__ Ws,
    const float* __restrict__ Wbh, const float* __restrict__ Wbs,
    const float* __restrict__ Wk,  const float* __restrict__ Wv,
    const float* __restrict__ W1,  const float* __restrict__ W2,
    __half* __restrict__ dWa_h, __half* __restrict__ dWa_l,
    __half* __restrict__ dWs,  __half* __restrict__ dWb,
    __half* __restrict__ dWk,  __half* __restrict__ dWv,
    __half* __restrict__ dW1,  __half* __restrict__ dW2)
{
    const int b = blockIdx.x;
    const float* src; __half* dh; __half* dl = nullptr; int b0;
    if      (b < CB_WS ){ src=Wa;  dh=dWa_h; dl=dWa_l; b0=CB_WA;  }
    else if (b < CB_WBH){ src=Ws;  dh=dWs;   b0=CB_WS;  }
    else if (b < CB_WBS){ src=Wbh; dh=dWb;   b0=CB_WBH; }
    else if (b < CB_WK ){ src=Wbs; dh=dWb + (size_t)CDIM*CDIM; b0=CB_WBS; }
    else if (b < CB_WV ){ src=Wk;  dh=dWk;   b0=CB_WK;  }
    else if (b < CB_W1 ){ src=Wv;  dh=dWv;   b0=CB_WV;  }
    else if (b < CB_W2 ){ src=W1;  dh=dW1;   b0=CB_W1;  }
    else                { src=W2;  dh=dW2;   b0=CB_W2;  }
    const long long i = ((long long)(b - b0)*256 + threadIdx.x)*8;
    conv8(src, dh, dl, i);
}

// ---------------- LN1 ----------------
__global__ void k_ln1(const float* __restrict__ x, const float* __restrict__ g1,
                      const float* __restrict__ b1)
{
    const int t = blockIdx.x;
    const int tid = threadIdx.x;
    if (t == 0 && tid < NEXP) g_cnt[tid] = 0;
    __shared__ float red[256];
    const float* xr = x + (size_t)t*CDIM;
    float v[4]; float s = 0.f;
#pragma unroll
    for (int q=0;q<4;q++){ v[q]=xr[tid+256*q]; s+=v[q]; }
    red[tid]=s; __syncthreads();
    for(int st=128;st>0;st>>=1){ if(tid<st) red[tid]+=red[tid+st]; __syncthreads(); }
    const float m = red[0]*(1.0f/CDIM);
    __syncthreads();
    float s2=0.f;
#pragma unroll
    for(int q=0;q<4;q++){ float d=v[q]-m; s2+=d*d; }
    red[tid]=s2; __syncthreads();
    for(int st=128;st>0;st>>=1){ if(tid<st) red[tid]+=red[tid+st]; __syncthreads(); }
    const float rstd = rsqrtf(red[0]*(1.0f/CDIM)+1e-5f);
#pragma unroll
    for(int q=0;q<4;q++){
        int i=tid+256*q;
        float xv=(v[q]-m)*rstd*g1[i]+b1[i];
        split_store(g_xln_h, g_xln_l, (size_t)t*CDIM+i, xv);
    }
}

// ---------------- LN2 + router (h stored hi-only) ----------------
__global__ void k_post1(const float* __restrict__ g2, const float* __restrict__ b2,
                        const float* __restrict__ w_conf, const float* __restrict__ w_diff,
                        const float* __restrict__ W_aff, const float* __restrict__ cap,
                        float* __restrict__ out)
{
    const int t = blockIdx.x;
    const int tid = threadIdx.x;
    __shared__ float red[256];
    __shared__ float sh[CDIM];
    __shared__ float sconf[NEXP], saff[NEXP];
    __shared__ float sdiff;
    const float* xr = g_x2 + (size_t)t*CDIM;
    float v[4]; float s=0.f;
#pragma unroll
    for(int q=0;q<4;q++){ v[q]=xr[tid+256*q]; s+=v[q]; }
    red[tid]=s; __syncthreads();
    for(int st=128;st>0;st>>=1){ if(tid<st) red[tid]+=red[tid+st]; __syncthreads(); }
    const float m=red[0]*(1.0f/CDIM);
    __syncthreads();
    float s2=0.f;
#pragma unroll
    for(int q=0;q<4;q++){ float d=v[q]-m; s2+=d*d; }
    red[tid]=s2; __syncthreads();
    for(int st=128;st>0;st>>=1){ if(tid<st) red[tid]+=red[tid+st]; __syncthreads(); }
    const float rstd=rsqrtf(red[0]*(1.0f/CDIM)+1e-5f);
#pragma unroll
    for(int q=0;q<4;q++){
        int i=tid+256*q;
        float hv=(v[q]-m)*rstd*g2[i]+b2[i];
        sh[i]=hv;
        g_hr_h[(size_t)t*2*CDIM+i] = __float2half(hv);
    }
    __syncthreads();
    const int w=tid>>5, lane=tid&31;
    float cd=0.f, ad=0.f, dd=0.f;
    for(int i=lane;i<CDIM;i+=32){
        float hv=sh[i];
        cd = fmaf(hv, w_conf[w*CDIM+i], cd);
        ad = fmaf(hv, W_aff[i*NEXP+w], ad);
        if(w==0) dd = fmaf(hv, w_diff[i], dd);
    }
#pragma unroll
    for(int o=16;o>0;o>>=1){
        cd += __shfl_down_sync(0xffffffffu, cd, o);
        ad += __shfl_down_sync(0xffffffffu, ad, o);
        dd += __shfl_down_sync(0xffffffffu, dd, o);
    }
    if(lane==0){ sconf[w]=cd; saff[w]=ad; if(w==0) sdiff=dd; }
    __syncthreads();
    if(tid<NEXP) out[OUT_AFF + t*NEXP + tid] = saff[tid];
    if(tid==0){
        float diff = fmaxf(sdiff,0.f) + log1pf(expf(-fabsf(sdiff)));
        float b0=-INFINITY, b1v=-INFINITY; int e0=0,e1=0;
#pragma unroll
        for(int e=0;e<NEXP;e++){
            float conf = 1.0f/(1.0f+expf(-sconf[e]));
            float bid = fmaf(conf, cap[e], saff[e]);
            if(bid>b0){ b1v=b0;e1=e0;b0=bid;e0=e; }
            else if(bid>b1v){ b1v=bid;e1=e; }
        }
        float ex = expf(b1v-b0);
        float w0 = 1.0f/(1.0f+ex);
        float w1 = ex/(1.0f+ex);
        out[OUT_WIN + 2*t]   = (float)e0;
        out[OUT_WIN + 2*t+1] = (float)e1;
        out[OUT_COST + t] = (b0*w0 + b1v*w1)*diff;
        out[OUT_DIFF + t] = diff;
        g_win[2*t]=e0; g_win[2*t+1]=e1;
        g_wt[2*t]=w0;  g_wt[2*t+1]=w1;
        atomicAdd(&g_cnt[e0],1);
        atomicAdd(&g_cnt[e1],1);
    }
}

// ---------------- routing setup/fill ----------------
__global__ void k_route_setup(){
    if(threadIdx.x==0){
        int o=0;
        for(int e=0;e<NEXP;e++){ g_off[e]=o; o+=g_cnt[e]; }
        g_off[NEXP]=o;
        int t1=0,t2=0;
        for(int e=0;e<NEXP;e++){
            g_cur[e]=g_off[e];
            int mt=(g_cnt[e]+255)>>8;
            int nt1=(e<ERWKV)?(HDIM>>7):(CDIM>>7);
            g_toff[0][e]=t1; t1+=mt*nt1;
            g_toff[1][e]=t2; t2+=mt*(CDIM>>7);
        }
        g_toff[0][NEXP]=t1; g_toff[1][NEXP]=t2;
        g_ctr[0]=0u; g_ctr[1]=0u;
    }
}
__global__ void k_route_fill(){
    int t = blockIdx.x*blockDim.x + threadIdx.x;
    if(t<BTOK){
#pragma unroll
        for(int r=0;r<2;r++){
            int e=g_win[2*t+r];
            int p=atomicAdd(&g_cur[e],1);
            g_tok[p]=t; g_gate[p]=g_wt[2*t+r]; g_rank[p]=r;
        }
    }
}

// ---------------- async chunk loader ----------------
template<int PASSES>
__device__ __forceinline__ void issue_chunk(uint32_t su, const long long* s_aoff,
    const __half* __restrict__ Ah, const __half* __restrict__ Al,
    const __half* __restrict__ Bh, const __half* __restrict__ Bl,
    int Nstride, int nb, int s, int c0)
{
    const int tid = threadIdx.x;
    const uint32_t STB = (PASSES==3)? STAGE3B : STAGE1B;
    const uint32_t boff = (PASSES==3)? (uint32_t)(4*ABUFE) : (uint32_t)(2*ABUFE);
    const uint32_t stage = su + (uint32_t)s*STB;
    const int nrows = (PASSES==3) ? 768 : 384;
    const int bstart = (PASSES==3) ? 512 : 256;
#pragma unroll
    for (int j=0; j<3; j++){
        const int r = tid + 256*j;
        if (r >= nrows) break;
        const __half* src;
        uint32_t dst;
        if (r < 256){
            src = Ah + s_aoff[r] + c0;
            dst = stage + (uint32_t)r*144u;
        } else if (PASSES==3 && r < 512){
            const int arow = r & 255;
            src = Al + s_aoff[arow] + c0;
            dst = stage + (uint32_t)(2*ABUFE) + (uint32_t)arow*144u;
        } else {
            const int br = r - bstart;
            const int brow = br & 127;
            const int k = brow>>1, hf = brow&1;
            const bool isBl = (PASSES==3) && (br >= 128);
            src = (isBl? Bl : Bh) + (long long)(c0+k)*Nstride + nb + hf*64;
            dst = stage + boff + (isBl? (uint32_t)BBUFB : 0u)
                  + (uint32_t)(k*272 + hf*128);
        }
#pragma unroll
        for (int i=0;i<8;i++){
            CP_ASYNC16(dst + i*16, src + i*8);
        }
    }
    CP_COMMIT();
}

// ---------------- wmma tile core (256x128 tile, warp 64x64) ----------------
template<int EPI, int PASSES>
__device__ void tc_tile(char* smem, uint32_t su,
    const __half* __restrict__ Ah, const __half* __restrict__ Al,
    int astride, int amode,
    const __half* __restrict__ Bh, const __half* __restrict__ Bl, int K, int Nstride,
    int mb, int nb, int base, int ne, int rwkv,
    const float* __restrict__ xsrc)
{
    const int tid = threadIdx.x;
    __half* sbuf = (__half*)smem;
    const int STB = (PASSES==3)? STAGE3B : STAGE1B;
    const int NSTG = (PASSES==3)? 2 : 3;
    long long* s_aoff = (long long*)(smem + NSTG*STB);
    {
        int r = tid;
        long long off;
        if (amode==0)      off = (long long)(mb+r)*astride;
        else if (amode==1){ int row=mb+r; int tk = (row<ne)? g_tok[base+row] : g_tok[base]; off=(long long)tk*astride; }
        else               off = (long long)(base+mb+r)*astride;
        s_aoff[r] = off;
    }
    __syncthreads();

    const int wid = tid>>5;
    const int m0w = (wid&3)*64;
    const int n0w = (wid>>2)*64;

    wmma::fragment<wmma::accumulator,16,16,16,float> acc[4][4];
#pragma unroll
    for (int i=0;i<4;i++)
#pragma unroll
        for (int j=0;j<4;j++) wmma::fill_fragment(acc[i][j], 0.0f);

    const int nch = K >> 6;
    issue_chunk<PASSES>(su, s_aoff, Ah, Al, Bh, Bl, Nstride, nb, 0, 0);
    if (NSTG==3 && nch>1)
        issue_chunk<PASSES>(su, s_aoff, Ah, Al, Bh, Bl, Nstride, nb, 1, 64);

    for (int c=0; c<nch; c++){
        const int s = c % NSTG;
        const int nx = c + NSTG - 1;
        if (nx < nch)
            issue_chunk<PASSES>(su, s_aoff, Ah, Al, Bh, Bl, Nstride, nb, nx % NSTG, nx<<6);
        int pend = nch-1-c; if (pend > NSTG-1) pend = NSTG-1;
        if (pend>=2)      CP_WAIT(2);
        else if (pend==1) CP_WAIT(1);
        else              CP_WAIT(0);
        __syncthreads();

        const __half* sAh = sbuf + (size_t)s*(STB/2);
        const __half* sAl = sAh + ABUFE;
        const __half* sBh = sAh + ((PASSES==3)? 2*ABUFE : ABUFE);
        const __half* sBl = sBh + BBUFB/2;
#pragma unroll
        for (int kk=0; kk<4; kk++){
            const int k0 = kk*16;
            wmma::fragment<wmma::matrix_a,16,16,16,__half,wmma::row_major> a_h[4], a_l[4];
#pragma unroll
            for (int mf=0; mf<4; mf++){
                wmma::load_matrix_sync(a_h[mf], sAh + (m0w+mf*16)*ROWE + k0, ROWE);
                if (PASSES==3)
                    wmma::load_matrix_sync(a_l[mf], sAl + (m0w+mf*16)*ROWE + k0, ROWE);
            }
#pragma unroll
            for (int nf=0; nf<4; nf++){
                wmma::fragment<wmma::matrix_b,16,16,16,__half,wmma::row_major> b_h;
                wmma::load_matrix_sync(b_h, sBh + k0*136 + n0w + nf*16, 136);
                if (PASSES==3){
                    wmma::fragment<wmma::matrix_b,16,16,16,__half,wmma::row_major> b_l;
                    wmma::load_matrix_sync(b_l, sBl + k0*136 + n0w + nf*16, 136);
#pragma unroll
                    for (int mf=0; mf<4; mf++){
                        wmma::mma_sync(acc[mf][nf], a_h[mf], b_h, acc[mf][nf]);
                        wmma::mma_sync(acc[mf][nf], a_h[mf], b_l, acc[mf][nf]);
                        wmma::mma_sync(acc[mf][nf], a_l[mf], b_h, acc[mf][nf]);
                    }
                } else {
#pragma unroll
                    for (int mf=0; mf<4; mf++){
                        wmma::mma_sync(acc[mf][nf], a_h[mf], b_h, acc[mf][nf]);
                    }
                }
            }
        }
        __syncthreads();
    }

    float* eps = (float*)smem;
#pragma unroll
    for (int mf=0; mf<4; mf++)
#pragma unroll
        for (int nf=0; nf<4; nf++)
            wmma::store_matrix_sync(eps + (size_t)(m0w+mf*16)*132 + n0w + nf*16, acc[mf][nf], 132, wmma::mem_row_major);
    __syncthreads();
    for (int i=tid; i<32768; i+=256){
        const int row = i>>7, col = i&127;
        const float v = eps[(size_t)row*132+col];
        if (EPI==0){
            size_t o = (size_t)(mb+row)*CDIM + nb + col;
            g_x2[o] = xsrc[o] + v;
        } else if (EPI==1){
            size_t o = (size_t)(mb+row)*2*CDIM + CDIM + nb + col;
            g_hr_h[o] = __float2half(v);
        } else if (EPI==2){
            size_t ho = (size_t)(mb+row)*2*CDIM + nb + col;
            float hrec = __half2float(g_hr_h[ho]);
            g_z_h[(size_t)(mb+row)*CDIM + nb + col] = __float2half(hrec + v);
        } else if (EPI==3){
            int r2 = mb+row;
            if (r2 < ne){
                float a;
                if (rwkv){ a = fmaxf(v,0.f); a = a*a; }
                else       a = gelu_tanh(v);
                g_mid_h[(size_t)(base+r2)*HDIM + nb + col] = __float2half(a);
            }
        } else {
            int r2 = mb+row;
            if (r2 < ne){
                int slot = base + r2;
                int tt = g_tok[slot];
                float gt = g_gate[slot];
                float* dst = g_rank[slot] ? g_slot1 : g_slot0;
                dst[(size_t)tt*CDIM + nb + col] = gt*v;
            }
        }
    }
    __syncthreads();
}

// ---------------- merged Wa(3-pass) + Ws(1-pass) kernel (interleaved CTAs) ----------------
__global__ __launch_bounds__(256,1) void k_dense_aw(
    const __half* __restrict__ xln_h, const __half* __restrict__ xln_l,
    const __half* __restrict__ Wa_h,  const __half* __restrict__ Wa_l,
    const __half* __restrict__ Ws_h,  const float* __restrict__ x)
{
    extern __shared__ char smem[];
    uint32_t su = smem_to_u32(smem);
    const int tile = blockIdx.x >> 1;
    const int nb = (tile & 7) * 128;
    const int mb = (tile >> 3) * 256;
    if ((blockIdx.x & 1) == 0){
        // Wa: 3-pass, residual epilogue into g_x2
        tc_tile<0,3>(smem, su, xln_h, xln_l, CDIM, 0, Wa_h, Wa_l, CDIM, CDIM,
                     mb, nb, 0, 1<<30, 0, x);
    } else {
        // Ws: 1-pass, rs epilogue into g_hr_h[:,1024:]
        tc_tile<1,1>(smem, su, xln_h, nullptr, CDIM, 0, Ws_h, nullptr, CDIM, CDIM,
                     mb, nb, 0, 1<<30, 0, nullptr);
    }
}

// ---------------- 1-pass dense (Wb) ----------------
template<int EPI>
__global__ __launch_bounds__(256,1) void k_dense1(
    const __half* __restrict__ Ah, int astride,
    const __half* __restrict__ Bh, int K, int Nstride)
{
    extern __shared__ char smem[];
    uint32_t su = smem_to_u32(smem);
    tc_tile<EPI,1>(smem, su, Ah, nullptr, astride, 0, Bh, nullptr, K, Nstride,
                 blockIdx.y*256, blockIdx.x*128, 0, 1<<30, 0, nullptr);
}

// ---------------- routed persistent grouped GEMM (1-pass fp16) ----------------
template<int STAGE>
__global__ __launch_bounds__(256,1) void k_routed(
    const __half* __restrict__ hr_h,
    const __half* __restrict__ z_h,
    const __half* __restrict__ mid_h,
    const __half* __restrict__ Wk_h,
    const __half* __restrict__ Wv_h,
    const __half* __restrict__ W1_h,
    const __half* __restrict__ W2_h)
{
    extern __shared__ char smem[];
    __shared__ int s_idx;
    uint32_t su = smem_to_u32(smem);
    const int total = g_toff[STAGE][NEXP];
    for(;;){
        if (threadIdx.x==0) s_idx = (int)atomicAdd(&g_ctr[STAGE], 1u);
        __syncthreads();
        const int idx = s_idx;
        if (idx >= total) break;
        int e = 0;
#pragma unroll
        for (int q=1;q<NEXP;q++) if (idx >= g_toff[STAGE][q]) e = q;
        const int local = idx - g_toff[STAGE][e];
        const int base = g_off[e];
        const int ne = g_off[e+1]-base;
        const bool rwkv = (e < ERWKV);
        const int ntl = (STAGE==0) ? (rwkv ? (HDIM>>7) : (CDIM>>7)) : (CDIM>>7);
        const int mb = (local/ntl)*256;
        const int nb = (local%ntl)*128;
        if (STAGE==0){
            const __half* Ah = rwkv ? hr_h : z_h;
            const int astride = rwkv ? 2*CDIM : CDIM;
            const __half* Bh = rwkv ? (Wk_h + (size_t)e*CDIM*HDIM) : (W1_h + (size_t)(e-ERWKV)*CDIM*CDIM);
            const int Nstride = rwkv ? HDIM : CDIM;
            tc_tile<3,1>(smem, su, Ah, nullptr, astride, 1, Bh, nullptr, CDIM, Nstride,
                       mb, nb, base, ne, rwkv?1:0, nullptr);
        } else {
            const int K = rwkv ? HDIM : CDIM;
            const __half* Bh = rwkv ? (Wv_h + (size_t)e*HDIM*CDIM) : (W2_h + (size_t)(e-ERWKV)*CDIM*CDIM);
            tc_tile<4,1>(smem, su, mid_h, nullptr, HDIM, 2, Bh, nullptr, K, CDIM,
                       mb, nb, base, ne, 0, nullptr);
        }
    }
}

// ---------------- epilogue combine ----------------
__global__ void k_final(const float* __restrict__ vf, float* __restrict__ out){
    const int i = blockIdx.x*256 + threadIdx.x;
    out[i]        = g_x2[i] + g_slot0[i] + g_slot1[i];
    out[OUT_VF+i] = vf[i];
}

// ---------------- launch ----------------
extern "C" void kernel_launch(void* const* d_in, const int* in_sizes, int n_in,
                              void* d_out, int out_size)
{
    const float* x     =(const float*)d_in[0];
    const float* vf    =(const float*)d_in[1];
    const float* cap   =(const float*)d_in[2];
    const float* ln1g  =(const float*)d_in[3];
    const float* ln1b  =(const float*)d_in[4];
    const float* ln2g  =(const float*)d_in[5];
    const float* ln2b  =(const float*)d_in[6];
    const float* Wa    =(const float*)d_in[7];
    const float* Ws    =(const float*)d_in[8];
    const float* wconf =(const float*)d_in[9];
    const float* wdiff =(const float*)d_in[10];
    const float* Waff  =(const float*)d_in[11];
    const float* Wbh   =(const float*)d_in[12];
    const float* Wbs   =(const float*)d_in[13];
    const float* Wk    =(const float*)d_in[14];
    const float* Wv    =(const float*)d_in[15];
    const float* W1    =(const float*)d_in[16];
    const float* W2    =(const float*)d_in[17];
    float* out=(float*)d_out;

    void *p_xln_h, *p_xln_l, *p_hr_h, *p_z_h, *p_mid_h;
    void *p_Wa_h, *p_Wa_l, *p_Ws_h, *p_Wb_h;
    void *p_Wk_h, *p_Wv_h, *p_W1_h, *p_W2_h;
    cudaGetSymbolAddress(&p_xln_h, g_xln_h); cudaGetSymbolAddress(&p_xln_l, g_xln_l);
    cudaGetSymbolAddress(&p_hr_h,  g_hr_h);
    cudaGetSymbolAddress(&p_z_h,   g_z_h);
    cudaGetSymbolAddress(&p_mid_h, g_mid_h);
    cudaGetSymbolAddress(&p_Wa_h, g_Wa_h);   cudaGetSymbolAddress(&p_Wa_l, g_Wa_l);
    cudaGetSymbolAddress(&p_Ws_h, g_Ws_h);
    cudaGetSymbolAddress(&p_Wb_h, g_Wb_h);
    cudaGetSymbolAddress(&p_Wk_h, g_Wk_h);
    cudaGetSymbolAddress(&p_Wv_h, g_Wv_h);
    cudaGetSymbolAddress(&p_W1_h, g_W1_h);
    cudaGetSymbolAddress(&p_W2_h, g_W2_h);

    cudaFuncSetAttribute(k_dense_aw, cudaFuncAttributeMaxDynamicSharedMemorySize, SMEM3_BYTES);
    cudaFuncSetAttribute(k_dense1<2>, cudaFuncAttributeMaxDynamicSharedMemorySize, SMEM1_BYTES);
    cudaFuncSetAttribute(k_routed<0>, cudaFuncAttributeMaxDynamicSharedMemorySize, SMEM1_BYTES);
    cudaFuncSetAttribute(k_routed<1>, cudaFuncAttributeMaxDynamicSharedMemorySize, SMEM1_BYTES);

    // one merged convert launch (all 8 weights)
    k_convert_all<<<CB_TOT,256>>>(Wa, Ws, Wbh, Wbs, Wk, Wv, W1, W2,
        (__half*)p_Wa_h, (__half*)p_Wa_l, (__half*)p_Ws_h, (__half*)p_Wb_h,
        (__half*)p_Wk_h, (__half*)p_Wv_h, (__half*)p_W1_h, (__half*)p_W2_h);

    k_ln1<<<BTOK,256>>>(x, ln1g, ln1b);

    // merged Wa + Ws (interleaved: even CTA -> Wa tile, odd -> Ws tile)
    k_dense_aw<<<256,256,SMEM3_BYTES>>>((__half*)p_xln_h, (__half*)p_xln_l,
        (__half*)p_Wa_h, (__half*)p_Wa_l, (__half*)p_Ws_h, x);

    k_post1<<<BTOK,256>>>(ln2g, ln2b, wconf, wdiff, Waff, cap, out);
    k_route_setup<<<1,32>>>();
    k_route_fill<<<(BTOK+255)/256,256>>>();

    dim3 gd(CDIM/128, BTOK/256);
    k_dense1<2><<<gd,256,SMEM1_BYTES>>>((__half*)p_hr_h, 2*CDIM, (__half*)p_Wb_h, 2*CDIM, CDIM);

    k_routed<0><<<148,256,SMEM1_BYTES>>>((__half*)p_hr_h, (__half*)p_z_h, (__half*)p_mid_h,
        (__half*)p_Wk_h,(__half*)p_Wv_h,(__half*)p_W1_h,(__half*)p_W2_h);
    k_routed<1><<<148,256,SMEM1_BYTES>>>((__half*)p_hr_h, (__half*)p_z_h, (__half*)p_mid_h,
        (__half*)p_Wk_h,(__half*)p_Wv_h,(__half*)p_W1_h,(__half*)p_W2_h);

    k_final<<<BTOK*CDIM/256,256>>>(vf, out);
}

// round 17
// speedup vs baseline: 1.0388x; 1.0388x over previous
#include <cuda_runtime.h>
#include <cuda_fp16.h>
#include <mma.h>
#include <math.h>
#include <stdint.h>

using namespace nvcuda;

#define BTOK 4096
#define CDIM 1024
#define HDIM 4096
#define NEXP 8
#define ERWKV 6
#define MAXS (2*BTOK)
#define MIDROWS (MAXS+256)

#define OUT_VF   (BTOK*CDIM)
#define OUT_WIN  (2*BTOK*CDIM)
#define OUT_COST (OUT_WIN + 2*BTOK)
#define OUT_DIFF (OUT_COST + BTOK)
#define OUT_AFF  (OUT_DIFF + BTOK)

// ---------------- SMEM layouts ----------------
#define ROWE   72                      // A row elements (144B)
#define ABUFE  (256*ROWE)              // 18432 elements (36864B) per A buffer
#define BBUFB  (64*272)                // 17408 bytes per B buffer
#define STAGE3B (4*ABUFE + 2*BBUFB)    // 3-pass stage (Wa), 2 stages
#define SMEM3_BYTES (2*STAGE3B + 2048) // 219136
#define STAGE1B (2*ABUFE + BBUFB)      // 1-pass stage, 3 stages
#define SMEM1_BYTES (3*STAGE1B + 2048) // 164864

// ---------------- scratch (static device memory) ----------------
__device__ __half g_xln_h[BTOK*CDIM], g_xln_l[BTOK*CDIM];
__device__ float g_x2[BTOK*CDIM];
__device__ __half g_hr_h[(size_t)BTOK*2*CDIM];   // [tok][0:1024)=h, [1024:2048)=rs (hi only)
__device__ __half g_z_h[BTOK*CDIM];
__device__ __half g_mid_h[(size_t)MIDROWS*HDIM];
__device__ float g_slot0[BTOK*CDIM], g_slot1[BTOK*CDIM];

// fp16 weights in ORIGINAL [K][N] layout (no transpose)
__device__ __half g_Wa_h[CDIM*CDIM], g_Wa_l[CDIM*CDIM];
__device__ __half g_Ws_h[CDIM*CDIM];
__device__ __half g_Wb_h[(size_t)2*CDIM*CDIM];
__device__ __half g_Wk_h[(size_t)ERWKV*CDIM*HDIM];
__device__ __half g_Wv_h[(size_t)ERWKV*HDIM*CDIM];
__device__ __half g_W1_h[2*CDIM*CDIM];
__device__ __half g_W2_h[2*CDIM*CDIM];

// routing
__device__ int   g_win[2*BTOK];
__device__ float g_wt [2*BTOK];
__device__ int   g_cnt[NEXP];
__device__ int   g_off[NEXP+1];
__device__ int   g_cur[NEXP];
__device__ int   g_tok[MAXS];
__device__ float g_gate[MAXS];
__device__ int   g_rank[MAXS];
__device__ int   g_toff[2][NEXP+1];
__device__ unsigned int g_ctr[2];

// ---------------- helpers ----------------
__device__ __forceinline__ uint32_t smem_to_u32(const void* p) {
    uint32_t a;
    asm("{ .reg .u64 t; cvta.to.shared.u64 t, %1; cvt.u32.u64 %0, t; }" : "=r"(a) : "l"(p));
    return a;
}
#define CP_ASYNC16(dst, src) \
    asm volatile("cp.async.cg.shared.global [%0], [%1], 16;" :: "r"(dst), "l"(src) : "memory")
#define CP_COMMIT() asm volatile("cp.async.commit_group;" ::: "memory")
#define CP_WAIT(n)  asm volatile("cp.async.wait_group %0;" :: "n"(n) : "memory")

__device__ __forceinline__ float gelu_tanh(float x){
    float x3 = x*x*x;
    return 0.5f*x*(1.0f + tanhf(0.7978845608028654f*(x + 0.044715f*x3)));
}
__device__ __forceinline__ void split_store(__half* ph, __half* pl, size_t o, float v){
    __half hi = __float2half(v);
    ph[o] = hi;
    pl[o] = __float2half(v - __half2float(hi));
}

// ---------------- merged prep: all 8 weight converts + LN1 in ONE launch ----------------
#define CBLK_C2   512                          // CDIM*CDIM / 2048
#define CBLK_KH   12288                        // ERWKV*CDIM*HDIM / 2048
#define CB_WA   0
#define CB_WS   (CB_WA  + CBLK_C2)
#define CB_WBH  (CB_WS  + CBLK_C2)
#define CB_WBS  (CB_WBH + CBLK_C2)
#define CB_WK   (CB_WBS + CBLK_C2)
#define CB_WV   (CB_WK  + CBLK_KH)
#define CB_W1   (CB_WV  + CBLK_KH)
#define CB_W2   (CB_W1  + 2*CBLK_C2)
#define CB_TOT  (CB_W2  + 2*CBLK_C2)           // 28672
#define PREP_TOT (CB_TOT + BTOK)

__device__ __forceinline__ void conv8(const float* __restrict__ src, __half* __restrict__ dh,
                                      __half* __restrict__ dl, long long i)
{
    float4 v0 = *(const float4*)(src+i);
    float4 v1 = *(const float4*)(src+i+4);
    __half2 a = __floats2half2_rn(v0.x, v0.y);
    __half2 b = __floats2half2_rn(v0.z, v0.w);
    __half2 c = __floats2half2_rn(v1.x, v1.y);
    __half2 d = __floats2half2_rn(v1.z, v1.w);
    uint4 o;
    o.x = *reinterpret_cast<unsigned*>(&a);
    o.y = *reinterpret_cast<unsigned*>(&b);
    o.z = *reinterpret_cast<unsigned*>(&c);
    o.w = *reinterpret_cast<unsigned*>(&d);
    *(uint4*)(dh+i) = o;
    if (dl){
        __half2 la = __floats2half2_rn(v0.x-__low2float(a), v0.y-__high2float(a));
        __half2 lb = __floats2half2_rn(v0.z-__low2float(b), v0.w-__high2float(b));
        __half2 lc = __floats2half2_rn(v1.x-__low2float(c), v1.y-__high2float(c));
        __half2 ld = __floats2half2_rn(v1.z-__low2float(d), v1.w-__high2float(d));
        uint4 ol;
        ol.x = *reinterpret_cast<unsigned*>(&la);
        ol.y = *reinterpret_cast<unsigned*>(&lb);
        ol.z = *reinterpret_cast<unsigned*>(&lc);
        ol.w = *reinterpret_cast<unsigned*>(&ld);
        *(uint4*)(dl+i) = ol;
    }
}

__global__ void k_prep(
    const float* __restrict__ Wa,  const float* __restrict__ Ws,
    const float* __restrict__ Wbh, const float* __restrict__ Wbs,
    const float* __restrict__ Wk,  const float* __restrict__ Wv,
    const float* __restrict__ W1,  const float* __restrict__ W2,
    __half* __restrict__ dWa_h, __half* __restrict__ dWa_l,
    __half* __restrict__ dWs,  __half* __restrict__ dWb,
    __half* __restrict__ dWk,  __half* __restrict__ dWv,
    __half* __restrict__ dW1,  __half* __restrict__ dW2,
    const float* __restrict__ x, const float* __restrict__ g1,
    const float* __restrict__ b1)
{
    const int b = blockIdx.x;
    const int tid = threadIdx.x;
    if (b < CB_TOT){
        const float* src; __half* dh; __half* dl = nullptr; int b0;
        if      (b < CB_WS ){ src=Wa;  dh=dWa_h; dl=dWa_l; b0=CB_WA;  }
        else if (b < CB_WBH){ src=Ws;  dh=dWs;   b0=CB_WS;  }
        else if (b < CB_WBS){ src=Wbh; dh=dWb;   b0=CB_WBH; }
        else if (b < CB_WK ){ src=Wbs; dh=dWb + (size_t)CDIM*CDIM; b0=CB_WBS; }
        else if (b < CB_WV ){ src=Wk;  dh=dWk;   b0=CB_WK;  }
        else if (b < CB_W1 ){ src=Wv;  dh=dWv;   b0=CB_WV;  }
        else if (b < CB_W2 ){ src=W1;  dh=dW1;   b0=CB_W1;  }
        else                { src=W2;  dh=dW2;   b0=CB_W2;  }
        const long long i = ((long long)(b - b0)*256 + tid)*8;
        conv8(src, dh, dl, i);
        return;
    }
    // LN1 part
    const int t = b - CB_TOT;
    if (t == 0 && tid < NEXP) g_cnt[tid] = 0;
    __shared__ float red[256];
    const float* xr = x + (size_t)t*CDIM;
    float v[4]; float s = 0.f;
#pragma unroll
    for (int q=0;q<4;q++){ v[q]=xr[tid+256*q]; s+=v[q]; }
    red[tid]=s; __syncthreads();
    for(int st=128;st>0;st>>=1){ if(tid<st) red[tid]+=red[tid+st]; __syncthreads(); }
    const float m = red[0]*(1.0f/CDIM);
    __syncthreads();
    float s2=0.f;
#pragma unroll
    for(int q=0;q<4;q++){ float d=v[q]-m; s2+=d*d; }
    red[tid]=s2; __syncthreads();
    for(int st=128;st>0;st>>=1){ if(tid<st) red[tid]+=red[tid+st]; __syncthreads(); }
    const float rstd = rsqrtf(red[0]*(1.0f/CDIM)+1e-5f);
#pragma unroll
    for(int q=0;q<4;q++){
        int i=tid+256*q;
        float xv=(v[q]-m)*rstd*g1[i]+b1[i];
        split_store(g_xln_h, g_xln_l, (size_t)t*CDIM+i, xv);
    }
}

// ---------------- LN2 + router (h stored hi-only) ----------------
__global__ void k_post1(const float* __restrict__ g2, const float* __restrict__ b2,
                        const float* __restrict__ w_conf, const float* __restrict__ w_diff,
                        const float* __restrict__ W_aff, const float* __restrict__ cap,
                        float* __restrict__ out)
{
    const int t = blockIdx.x;
    const int tid = threadIdx.x;
    __shared__ float red[256];
    __shared__ float sh[CDIM];
    __shared__ float sconf[NEXP], saff[NEXP];
    __shared__ float sdiff;
    const float* xr = g_x2 + (size_t)t*CDIM;
    float v[4]; float s=0.f;
#pragma unroll
    for(int q=0;q<4;q++){ v[q]=xr[tid+256*q]; s+=v[q]; }
    red[tid]=s; __syncthreads();
    for(int st=128;st>0;st>>=1){ if(tid<st) red[tid]+=red[tid+st]; __syncthreads(); }
    const float m=red[0]*(1.0f/CDIM);
    __syncthreads();
    float s2=0.f;
#pragma unroll
    for(int q=0;q<4;q++){ float d=v[q]-m; s2+=d*d; }
    red[tid]=s2; __syncthreads();
    for(int st=128;st>0;st>>=1){ if(tid<st) red[tid]+=red[tid+st]; __syncthreads(); }
    const float rstd=rsqrtf(red[0]*(1.0f/CDIM)+1e-5f);
#pragma unroll
    for(int q=0;q<4;q++){
        int i=tid+256*q;
        float hv=(v[q]-m)*rstd*g2[i]+b2[i];
        sh[i]=hv;
        g_hr_h[(size_t)t*2*CDIM+i] = __float2half(hv);
    }
    __syncthreads();
    const int w=tid>>5, lane=tid&31;
    float cd=0.f, ad=0.f, dd=0.f;
    for(int i=lane;i<CDIM;i+=32){
        float hv=sh[i];
        cd = fmaf(hv, w_conf[w*CDIM+i], cd);
        ad = fmaf(hv, W_aff[i*NEXP+w], ad);
        if(w==0) dd = fmaf(hv, w_diff[i], dd);
    }
#pragma unroll
    for(int o=16;o>0;o>>=1){
        cd += __shfl_down_sync(0xffffffffu, cd, o);
        ad += __shfl_down_sync(0xffffffffu, ad, o);
        dd += __shfl_down_sync(0xffffffffu, dd, o);
    }
    if(lane==0){ sconf[w]=cd; saff[w]=ad; if(w==0) sdiff=dd; }
    __syncthreads();
    if(tid<NEXP) out[OUT_AFF + t*NEXP + tid] = saff[tid];
    if(tid==0){
        float diff = fmaxf(sdiff,0.f) + log1pf(expf(-fabsf(sdiff)));
        float b0=-INFINITY, b1v=-INFINITY; int e0=0,e1=0;
#pragma unroll
        for(int e=0;e<NEXP;e++){
            float conf = 1.0f/(1.0f+expf(-sconf[e]));
            float bid = fmaf(conf, cap[e], saff[e]);
            if(bid>b0){ b1v=b0;e1=e0;b0=bid;e0=e; }
            else if(bid>b1v){ b1v=bid;e1=e; }
        }
        float ex = expf(b1v-b0);
        float w0 = 1.0f/(1.0f+ex);
        float w1 = ex/(1.0f+ex);
        out[OUT_WIN + 2*t]   = (float)e0;
        out[OUT_WIN + 2*t+1] = (float)e1;
        out[OUT_COST + t] = (b0*w0 + b1v*w1)*diff;
        out[OUT_DIFF + t] = diff;
        g_win[2*t]=e0; g_win[2*t+1]=e1;
        g_wt[2*t]=w0;  g_wt[2*t+1]=w1;
        atomicAdd(&g_cnt[e0],1);
        atomicAdd(&g_cnt[e1],1);
    }
}

// ---------------- routing setup/fill ----------------
__global__ void k_route_setup(){
    if(threadIdx.x==0){
        int o=0;
        for(int e=0;e<NEXP;e++){ g_off[e]=o; o+=g_cnt[e]; }
        g_off[NEXP]=o;
        int t1=0,t2=0;
        for(int e=0;e<NEXP;e++){
            g_cur[e]=g_off[e];
            int mt=(g_cnt[e]+255)>>8;
            int nt1=(e<ERWKV)?(HDIM>>7):(CDIM>>7);
            g_toff[0][e]=t1; t1+=mt*nt1;
            g_toff[1][e]=t2; t2+=mt*(CDIM>>7);
        }
        g_toff[0][NEXP]=t1; g_toff[1][NEXP]=t2;
        g_ctr[0]=0u; g_ctr[1]=0u;
    }
}
__global__ void k_route_fill(){
    int t = blockIdx.x*blockDim.x + threadIdx.x;
    if(t<BTOK){
#pragma unroll
        for(int r=0;r<2;r++){
            int e=g_win[2*t+r];
            int p=atomicAdd(&g_cur[e],1);
            g_tok[p]=t; g_gate[p]=g_wt[2*t+r]; g_rank[p]=r;
        }
    }
}

// ---------------- async chunk loader ----------------
template<int PASSES>
__device__ __forceinline__ void issue_chunk(uint32_t su, const long long* s_aoff,
    const __half* __restrict__ Ah, const __half* __restrict__ Al,
    const __half* __restrict__ Bh, const __half* __restrict__ Bl,
    int Nstride, int nb, int s, int c0)
{
    const int tid = threadIdx.x;
    const uint32_t STB = (PASSES==3)? STAGE3B : STAGE1B;
    const uint32_t boff = (PASSES==3)? (uint32_t)(4*ABUFE) : (uint32_t)(2*ABUFE);
    const uint32_t stage = su + (uint32_t)s*STB;
    const int nrows = (PASSES==3) ? 768 : 384;
    const int bstart = (PASSES==3) ? 512 : 256;
#pragma unroll
    for (int j=0; j<3; j++){
        const int r = tid + 256*j;
        if (r >= nrows) break;
        const __half* src;
        uint32_t dst;
        if (r < 256){
            src = Ah + s_aoff[r] + c0;
            dst = stage + (uint32_t)r*144u;
        } else if (PASSES==3 && r < 512){
            const int arow = r & 255;
            src = Al + s_aoff[arow] + c0;
            dst = stage + (uint32_t)(2*ABUFE) + (uint32_t)arow*144u;
        } else {
            const int br = r - bstart;
            const int brow = br & 127;
            const int k = brow>>1, hf = brow&1;
            const bool isBl = (PASSES==3) && (br >= 128);
            src = (isBl? Bl : Bh) + (long long)(c0+k)*Nstride + nb + hf*64;
            dst = stage + boff + (isBl? (uint32_t)BBUFB : 0u)
                  + (uint32_t)(k*272 + hf*128);
        }
#pragma unroll
        for (int i=0;i<8;i++){
            CP_ASYNC16(dst + i*16, src + i*8);
        }
    }
    CP_COMMIT();
}

// ---------------- wmma tile core (256x128 tile, warp 64x64) ----------------
template<int EPI, int PASSES>
__device__ void tc_tile(char* smem, uint32_t su,
    const __half* __restrict__ Ah, const __half* __restrict__ Al,
    int astride, int amode,
    const __half* __restrict__ Bh, const __half* __restrict__ Bl, int K, int Nstride,
    int mb, int nb, int base, int ne, int rwkv,
    const float* __restrict__ xsrc)
{
    const int tid = threadIdx.x;
    __half* sbuf = (__half*)smem;
    const int STB = (PASSES==3)? STAGE3B : STAGE1B;
    const int NSTG = (PASSES==3)? 2 : 3;
    long long* s_aoff = (long long*)(smem + NSTG*STB);
    {
        int r = tid;
        long long off;
        if (amode==0)      off = (long long)(mb+r)*astride;
        else if (amode==1){ int row=mb+r; int tk = (row<ne)? g_tok[base+row] : g_tok[base]; off=(long long)tk*astride; }
        else               off = (long long)(base+mb+r)*astride;
        s_aoff[r] = off;
    }
    __syncthreads();

    const int wid = tid>>5;
    const int m0w = (wid&3)*64;
    const int n0w = (wid>>2)*64;

    wmma::fragment<wmma::accumulator,16,16,16,float> acc[4][4];
#pragma unroll
    for (int i=0;i<4;i++)
#pragma unroll
        for (int j=0;j<4;j++) wmma::fill_fragment(acc[i][j], 0.0f);

    const int nch = K >> 6;
    issue_chunk<PASSES>(su, s_aoff, Ah, Al, Bh, Bl, Nstride, nb, 0, 0);
    if (NSTG==3 && nch>1)
        issue_chunk<PASSES>(su, s_aoff, Ah, Al, Bh, Bl, Nstride, nb, 1, 64);

    for (int c=0; c<nch; c++){
        const int s = c % NSTG;
        const int nx = c + NSTG - 1;
        if (nx < nch)
            issue_chunk<PASSES>(su, s_aoff, Ah, Al, Bh, Bl, Nstride, nb, nx % NSTG, nx<<6);
        int pend = nch-1-c; if (pend > NSTG-1) pend = NSTG-1;
        if (pend>=2)      CP_WAIT(2);
        else if (pend==1) CP_WAIT(1);
        else              CP_WAIT(0);
        __syncthreads();

        const __half* sAh = sbuf + (size_t)s*(STB/2);
        const __half* sAl = sAh + ABUFE;
        const __half* sBh = sAh + ((PASSES==3)? 2*ABUFE : ABUFE);
        const __half* sBl = sBh + BBUFB/2;
#pragma unroll
        for (int kk=0; kk<4; kk++){
            const int k0 = kk*16;
            wmma::fragment<wmma::matrix_a,16,16,16,__half,wmma::row_major> a_h[4], a_l[4];
#pragma unroll
            for (int mf=0; mf<4; mf++){
                wmma::load_matrix_sync(a_h[mf], sAh + (m0w+mf*16)*ROWE + k0, ROWE);
                if (PASSES==3)
                    wmma::load_matrix_sync(a_l[mf], sAl + (m0w+mf*16)*ROWE + k0, ROWE);
            }
#pragma unroll
            for (int nf=0; nf<4; nf++){
                wmma::fragment<wmma::matrix_b,16,16,16,__half,wmma::row_major> b_h;
                wmma::load_matrix_sync(b_h, sBh + k0*136 + n0w + nf*16, 136);
                if (PASSES==3){
                    wmma::fragment<wmma::matrix_b,16,16,16,__half,wmma::row_major> b_l;
                    wmma::load_matrix_sync(b_l, sBl + k0*136 + n0w + nf*16, 136);
#pragma unroll
                    for (int mf=0; mf<4; mf++){
                        wmma::mma_sync(acc[mf][nf], a_h[mf], b_h, acc[mf][nf]);
                        wmma::mma_sync(acc[mf][nf], a_h[mf], b_l, acc[mf][nf]);
                        wmma::mma_sync(acc[mf][nf], a_l[mf], b_h, acc[mf][nf]);
                    }
                } else {
#pragma unroll
                    for (int mf=0; mf<4; mf++){
                        wmma::mma_sync(acc[mf][nf], a_h[mf], b_h, acc[mf][nf]);
                    }
                }
            }
        }
        __syncthreads();
    }

    float* eps = (float*)smem;
#pragma unroll
    for (int mf=0; mf<4; mf++)
#pragma unroll
        for (int nf=0; nf<4; nf++)
            wmma::store_matrix_sync(eps + (size_t)(m0w+mf*16)*132 + n0w + nf*16, acc[mf][nf], 132, wmma::mem_row_major);
    __syncthreads();
    for (int i=tid; i<32768; i+=256){
        const int row = i>>7, col = i&127;
        const float v = eps[(size_t)row*132+col];
        if (EPI==0){
            size_t o = (size_t)(mb+row)*CDIM + nb + col;
            g_x2[o] = xsrc[o] + v;
        } else if (EPI==1){
            size_t o = (size_t)(mb+row)*2*CDIM + CDIM + nb + col;
            g_hr_h[o] = __float2half(v);
        } else if (EPI==2){
            size_t ho = (size_t)(mb+row)*2*CDIM + nb + col;
            float hrec = __half2float(g_hr_h[ho]);
            g_z_h[(size_t)(mb+row)*CDIM + nb + col] = __float2half(hrec + v);
        } else if (EPI==3){
            int r2 = mb+row;
            if (r2 < ne){
                float a;
                if (rwkv){ a = fmaxf(v,0.f); a = a*a; }
                else       a = gelu_tanh(v);
                g_mid_h[(size_t)(base+r2)*HDIM + nb + col] = __float2half(a);
            }
        } else {
            int r2 = mb+row;
            if (r2 < ne){
                int slot = base + r2;
                int tt = g_tok[slot];
                float gt = g_gate[slot];
                float* dst = g_rank[slot] ? g_slot1 : g_slot0;
                dst[(size_t)tt*CDIM + nb + col] = gt*v;
            }
        }
    }
    __syncthreads();
}

// ---------------- dense GEMM kernels ----------------
__global__ __launch_bounds__(256,1) void k_dense3(
    const __half* __restrict__ Ah, const __half* __restrict__ Al, int astride,
    const __half* __restrict__ Bh, const __half* __restrict__ Bl, int K, int Nstride,
    const float* __restrict__ xsrc)
{
    extern __shared__ char smem[];
    uint32_t su = smem_to_u32(smem);
    tc_tile<0,3>(smem, su, Ah, Al, astride, 0, Bh, Bl, K, Nstride,
                 blockIdx.y*256, blockIdx.x*128, 0, 1<<30, 0, xsrc);
}
template<int EPI>
__global__ __launch_bounds__(256,1) void k_dense1(
    const __half* __restrict__ Ah, int astride,
    const __half* __restrict__ Bh, int K, int Nstride)
{
    extern __shared__ char smem[];
    uint32_t su = smem_to_u32(smem);
    tc_tile<EPI,1>(smem, su, Ah, nullptr, astride, 0, Bh, nullptr, K, Nstride,
                 blockIdx.y*256, blockIdx.x*128, 0, 1<<30, 0, nullptr);
}

// ---------------- routed persistent grouped GEMM (1-pass fp16) ----------------
template<int STAGE>
__global__ __launch_bounds__(256,1) void k_routed(
    const __half* __restrict__ hr_h,
    const __half* __restrict__ z_h,
    const __half* __restrict__ mid_h,
    const __half* __restrict__ Wk_h,
    const __half* __restrict__ Wv_h,
    const __half* __restrict__ W1_h,
    const __half* __restrict__ W2_h)
{
    extern __shared__ char smem[];
    __shared__ int s_idx;
    uint32_t su = smem_to_u32(smem);
    const int total = g_toff[STAGE][NEXP];
    for(;;){
        if (threadIdx.x==0) s_idx = (int)atomicAdd(&g_ctr[STAGE], 1u);
        __syncthreads();
        const int idx = s_idx;
        if (idx >= total) break;
        int e = 0;
#pragma unroll
        for (int q=1;q<NEXP;q++) if (idx >= g_toff[STAGE][q]) e = q;
        const int local = idx - g_toff[STAGE][e];
        const int base = g_off[e];
        const int ne = g_off[e+1]-base;
        const bool rwkv = (e < ERWKV);
        const int ntl = (STAGE==0) ? (rwkv ? (HDIM>>7) : (CDIM>>7)) : (CDIM>>7);
        const int mb = (local/ntl)*256;
        const int nb = (local%ntl)*128;
        if (STAGE==0){
            const __half* Ah = rwkv ? hr_h : z_h;
            const int astride = rwkv ? 2*CDIM : CDIM;
            const __half* Bh = rwkv ? (Wk_h + (size_t)e*CDIM*HDIM) : (W1_h + (size_t)(e-ERWKV)*CDIM*CDIM);
            const int Nstride = rwkv ? HDIM : CDIM;
            tc_tile<3,1>(smem, su, Ah, nullptr, astride, 1, Bh, nullptr, CDIM, Nstride,
                       mb, nb, base, ne, rwkv?1:0, nullptr);
        } else {
            const int K = rwkv ? HDIM : CDIM;
            const __half* Bh = rwkv ? (Wv_h + (size_t)e*HDIM*CDIM) : (W2_h + (size_t)(e-ERWKV)*CDIM*CDIM);
            tc_tile<4,1>(smem, su, mid_h, nullptr, HDIM, 2, Bh, nullptr, K, CDIM,
                       mb, nb, base, ne, 0, nullptr);
        }
    }
}

// ---------------- epilogue combine ----------------
__global__ void k_final(const float* __restrict__ vf, float* __restrict__ out){
    const int i = blockIdx.x*256 + threadIdx.x;
    out[i]        = g_x2[i] + g_slot0[i] + g_slot1[i];
    out[OUT_VF+i] = vf[i];
}

// ---------------- launch ----------------
extern "C" void kernel_launch(void* const* d_in, const int* in_sizes, int n_in,
                              void* d_out, int out_size)
{
    const float* x     =(const float*)d_in[0];
    const float* vf    =(const float*)d_in[1];
    const float* cap   =(const float*)d_in[2];
    const float* ln1g  =(const float*)d_in[3];
    const float* ln1b  =(const float*)d_in[4];
    const float* ln2g  =(const float*)d_in[5];
    const float* ln2b  =(const float*)d_in[6];
    const float* Wa    =(const float*)d_in[7];
    const float* Ws    =(const float*)d_in[8];
    const float* wconf =(const float*)d_in[9];
    const float* wdiff =(const float*)d_in[10];
    const float* Waff  =(const float*)d_in[11];
    const float* Wbh   =(const float*)d_in[12];
    const float* Wbs   =(const float*)d_in[13];
    const float* Wk    =(const float*)d_in[14];
    const float* Wv    =(const float*)d_in[15];
    const float* W1    =(const float*)d_in[16];
    const float* W2    =(const float*)d_in[17];
    float* out=(float*)d_out;

    void *p_xln_h, *p_xln_l, *p_hr_h, *p_z_h, *p_mid_h;
    void *p_Wa_h, *p_Wa_l, *p_Ws_h, *p_Wb_h;
    void *p_Wk_h, *p_Wv_h, *p_W1_h, *p_W2_h;
    cudaGetSymbolAddress(&p_xln_h, g_xln_h); cudaGetSymbolAddress(&p_xln_l, g_xln_l);
    cudaGetSymbolAddress(&p_hr_h,  g_hr_h);
    cudaGetSymbolAddress(&p_z_h,   g_z_h);
    cudaGetSymbolAddress(&p_mid_h, g_mid_h);
    cudaGetSymbolAddress(&p_Wa_h, g_Wa_h);   cudaGetSymbolAddress(&p_Wa_l, g_Wa_l);
    cudaGetSymbolAddress(&p_Ws_h, g_Ws_h);
    cudaGetSymbolAddress(&p_Wb_h, g_Wb_h);
    cudaGetSymbolAddress(&p_Wk_h, g_Wk_h);
    cudaGetSymbolAddress(&p_Wv_h, g_Wv_h);
    cudaGetSymbolAddress(&p_W1_h, g_W1_h);
    cudaGetSymbolAddress(&p_W2_h, g_W2_h);

    cudaFuncSetAttribute(k_dense3, cudaFuncAttributeMaxDynamicSharedMemorySize, SMEM3_BYTES);
    cudaFuncSetAttribute(k_dense1<1>, cudaFuncAttributeMaxDynamicSharedMemorySize, SMEM1_BYTES);
    cudaFuncSetAttribute(k_dense1<2>, cudaFuncAttributeMaxDynamicSharedMemorySize, SMEM1_BYTES);
    cudaFuncSetAttribute(k_routed<0>, cudaFuncAttributeMaxDynamicSharedMemorySize, SMEM1_BYTES);
    cudaFuncSetAttribute(k_routed<1>, cudaFuncAttributeMaxDynamicSharedMemorySize, SMEM1_BYTES);

    // merged prep: 8 weight converts + LN1 in one launch
    k_prep<<<PREP_TOT,256>>>(Wa, Ws, Wbh, Wbs, Wk, Wv, W1, W2,
        (__half*)p_Wa_h, (__half*)p_Wa_l, (__half*)p_Ws_h, (__half*)p_Wb_h,
        (__half*)p_Wk_h, (__half*)p_Wv_h, (__half*)p_W1_h, (__half*)p_W2_h,
        x, ln1g, ln1b);

    dim3 gd(CDIM/128, BTOK/256);
    k_dense3<<<gd,256,SMEM3_BYTES>>>((__half*)p_xln_h, (__half*)p_xln_l, CDIM,
                                     (__half*)p_Wa_h, (__half*)p_Wa_l, CDIM, CDIM, x);
    k_dense1<1><<<gd,256,SMEM1_BYTES>>>((__half*)p_xln_h, CDIM, (__half*)p_Ws_h, CDIM, CDIM);

    k_post1<<<BTOK,256>>>(ln2g, ln2b, wconf, wdiff, Waff, cap, out);
    k_route_setup<<<1,32>>>();
    k_route_fill<<<(BTOK+255)/256,256>>>();

    k_dense1<2><<<gd,256,SMEM1_BYTES>>>((__half*)p_hr_h, 2*CDIM, (__half*)p_Wb_h, 2*CDIM, CDIM);

    k_routed<0><<<148,256,SMEM1_BYTES>>>((__half*)p_hr_h, (__half*)p_z_h, (__half*)p_mid_h,
        (__half*)p_Wk_h,(__half*)p_Wv_h,(__half*)p_W1_h,(__half*)p_W2_h);
    k_routed<1><<<148,256,SMEM1_BYTES>>>((__half*)p_hr_h, (__half*)p_z_h, (__half*)p_mid_h,
        (__half*)p_Wk_h,(__half*)p_Wv_h,(__half*)p_W1_h,(__half*)p_W2_h);

    k_final<<<BTOK*CDIM/256,256>>>(vf, out);
}